// round 9
// baseline (speedup 1.0000x reference)
#include <cuda_runtime.h>
#include <math.h>
#include <stdint.h>

// Problem shapes (fixed by the dataset)
#define T_    4096
#define D_    1024
#define H_    512
#define E_    32
#define TOPK_ 4
#define CAP_  2048
#define HS_   1024
#define P_    (T_*TOPK_)

// ---------------- scratch (device globals) ----------------------------------
__device__ int   g_topk_idx[P_];
__device__ float g_topk_w[P_];
__device__ float g_pair_wc[P_];
__device__ int   g_counts[E_];
__device__ int   g_rows_token[E_*CAP_];
__device__ int   g_slot_pair[E_*CAP_];
__device__ __align__(256) float g_xr[(size_t)T_*D_];          // rna(x)
__device__ __align__(256) float g_Gs[(size_t)T_*HS_];         // shared hidden (rna)
__device__ __align__(256) float g_Gbuf[(size_t)E_*CAP_*H_];   // expert hidden (rna)
__device__ __align__(256) float g_Obuf[(size_t)P_*D_];        // per-pair outputs

// ---------------- helpers ----------------------------------------------------
__device__ __forceinline__ uint32_t smem_u32(const void* p) {
    uint32_t a;
    asm("{ .reg .u64 t; cvta.to.shared.u64 t, %1; cvt.u32.u64 %0, t; }"
        : "=r"(a) : "l"(p));
    return a;
}
__device__ __forceinline__ uint32_t rna_b(float v) {
    uint32_t o;
    asm("cvt.rna.tf32.f32 %0, %1;" : "=r"(o) : "f"(v));
    return o;
}
__device__ __forceinline__ float rna_f(float v) {
    return __uint_as_float(rna_b(v));
}
__device__ __forceinline__ void cp16(uint32_t saddr, const void* g) {
    asm volatile("cp.async.cg.shared.global [%0], [%1], 16;"
                 :: "r"(saddr), "l"(g) : "memory");
}
__device__ __forceinline__ void cp_commit() {
    asm volatile("cp.async.commit_group;" ::: "memory");
}
template<int N>
__device__ __forceinline__ void cp_wait() {
    asm volatile("cp.async.wait_group %0;" :: "n"(N) : "memory");
}
__device__ __forceinline__ void mma8(float* c, const uint32_t* a, const uint32_t* b) {
    asm volatile(
        "mma.sync.aligned.m16n8k8.row.col.f32.tf32.tf32.f32 "
        "{%0,%1,%2,%3}, {%4,%5,%6,%7}, {%8,%9}, {%0,%1,%2,%3};"
        : "+f"(c[0]), "+f"(c[1]), "+f"(c[2]), "+f"(c[3])
        : "r"(a[0]), "r"(a[1]), "r"(a[2]), "r"(a[3]), "r"(b[0]), "r"(b[1]));
}
__device__ __forceinline__ float silu_f(float h) {
    return h / (1.0f + expf(-h));
}

// ---------------- prepass: rna round-copy (x only; cheap) -------------------
__global__ __launch_bounds__(256) void round_copy(const float4* __restrict__ src,
                                                  float4* __restrict__ dst, int n4)
{
    int i = blockIdx.x * 256 + threadIdx.x;
    if (i < n4) {
        float4 v = src[i];
        v.x = rna_f(v.x); v.y = rna_f(v.y); v.z = rna_f(v.z); v.w = rna_f(v.w);
        dst[i] = v;
    }
}

// ---------------- gating -----------------------------------------------------
__global__ __launch_bounds__(256) void gate_kernel(const float* __restrict__ x,
                                                   const float* __restrict__ Wg)
{
    __shared__ float xs[D_];
    __shared__ float red[8][E_];
    __shared__ float probs[E_];
    int t = blockIdx.x, tid = threadIdx.x;
    ((float4*)xs)[tid] = ((const float4*)(x + (size_t)t * D_))[tid];
    __syncthreads();
    int e = tid & 31, seg = tid >> 5, k0 = seg * (D_/8);
    float acc = 0.f;
    #pragma unroll 8
    for (int k = 0; k < D_/8; ++k)
        acc = fmaf(xs[k0 + k], Wg[(size_t)(k0 + k) * E_ + e], acc);
    red[seg][e] = acc;
    __syncthreads();
    if (tid < E_) {
        float s = 0.f;
        #pragma unroll
        for (int i = 0; i < 8; ++i) s += red[i][tid];
        float m = s;
        #pragma unroll
        for (int o = 16; o > 0; o >>= 1) m = fmaxf(m, __shfl_xor_sync(0xffffffffu, m, o));
        float p = expf(s - m);
        float sum = p;
        #pragma unroll
        for (int o = 16; o > 0; o >>= 1) sum += __shfl_xor_sync(0xffffffffu, sum, o);
        probs[tid] = p / sum;
    }
    __syncthreads();
    if (tid == 0) {
        bool used[E_];
        #pragma unroll
        for (int i = 0; i < E_; ++i) used[i] = false;
        for (int k = 0; k < TOPK_; ++k) {
            float best = -1.f; int bi = 0;
            for (int i = 0; i < E_; ++i)
                if (!used[i] && probs[i] > best) { best = probs[i]; bi = i; }
            used[bi] = true;
            g_topk_idx[t * TOPK_ + k] = bi;
            g_topk_w  [t * TOPK_ + k] = best;
        }
    }
}

__global__ void zero_counts_kernel() {
    if (threadIdx.x < E_) g_counts[threadIdx.x] = 0;
}

__global__ void dispatch_kernel() {
    int p = blockIdx.x * blockDim.x + threadIdx.x;
    if (p >= P_) return;
    int e   = g_topk_idx[p];
    int tok = p >> 2;
    int pos = atomicAdd(&g_counts[e], 1);
    if (pos < CAP_) {
        int slot = e * CAP_ + pos;
        g_rows_token[slot] = tok;
        g_slot_pair[slot]  = p;
        g_pair_wc[p]       = g_topk_w[p];
    } else {
        g_pair_wc[p] = 0.0f;
    }
}

// ---------------- unified tf32 mma.sync GEMM (256 threads, 64-row tiles) ----
// MODE 0: Gs   = rna(silu(x@Ws1)*(x@Ws3))   dual, CTA 128x128, warp 64x32
// MODE 1: y    = Gs@Ws2                     single, CTA 256x128, warp 64x64
// MODE 2: Gbuf = rna(silu(xg@W1)*(xg@W3))   dual, gather
// MODE 3: Obuf = Gbuf@W2                    single
// 8 warps. K-chunk 32; stages: dual 3, single 4. 8 MACs/smem-byte.
// A operands pre-rounded tf32; B (weights) rounded in-register per fragment.
template<int MODE>
__global__ void __launch_bounds__(256, 1)
gemm_mma(const float* __restrict__ A,
         const float* __restrict__ B1,
         const float* __restrict__ B3,
         float* __restrict__ Out)
{
    constexpr bool DUAL   = (MODE == 0 || MODE == 2);
    constexpr bool EXPERT = (MODE >= 2);
    constexpr int  KLEN   = (MODE == 3) ? H_ : ((MODE == 1) ? HS_ : D_);
    constexpr int  NTOT   = (MODE == 0) ? HS_ : ((MODE == 2) ? H_ : D_);
    constexpr int  NCH    = KLEN / 32;
    constexpr int  S      = DUAL ? 3 : 4;            // pipeline stages
    constexpr int  MROWS  = DUAL ? 128 : 256;        // CTA M tile
    constexpr int  NT     = DUAL ? 4 : 8;            // n8 tiles per warp
    constexpr int  WCN    = DUAL ? 4 : 2;            // warps along N
    constexpr int  AF     = 36;
    constexpr int  BF     = 136;
    constexpr int  ABYTES = MROWS * AF * 4;
    constexpr int  BBYTES = 32 * BF * 4;             // 17408
    constexpr int  STAGE  = ABYTES + (DUAL ? 2 : 1) * BBYTES;

    extern __shared__ char smem[];
    const uint32_t sb0 = smem_u32(smem);

    const int tid = threadIdx.x;
    const int wid = tid >> 5, lane = tid & 31;
    const int e   = EXPERT ? blockIdx.z : 0;
    const int nc  = EXPERT ? min(g_counts[e], CAP_) : (1 << 30);
    const int r0  = blockIdx.y * MROWS;
    if (EXPERT && r0 >= nc) return;
    const int n0  = blockIdx.x * 128;

    // ---- cp.async addressing ----
    // A: dual: 2 thr/row (64B each, 4 cp16); single: 1 thr/row (128B, 8 cp16)
    constexpr int ATHR_PER_ROW = DUAL ? 2 : 1;
    constexpr int ACP = 32 / (ATHR_PER_ROW * 4);     // cp16 per thread (4 or 8)
    const int alr = DUAL ? (tid >> 1) : tid;
    const int alc = DUAL ? ((tid & 1) * 16) : 0;     // float offset within row
    const float* asrc;
    if (MODE == 2) {
        int gr  = min(r0 + alr, nc - 1);
        int tok = g_rows_token[e * CAP_ + gr];
        asrc = A + (size_t)tok * D_ + alc;
    } else if (MODE == 3) {
        asrc = A + ((size_t)e * CAP_ + r0 + alr) * H_ + alc;
    } else {
        asrc = A + (size_t)(r0 + alr) * KLEN + alc;
    }
    // B: 8 thr/row x 64B (4 cp16)
    const int bkr = tid >> 3, bcf = (tid & 7) * 16;
    const size_t eb = (MODE == 2) ? (size_t)e * D_ * H_
                    : ((MODE == 3) ? (size_t)e * H_ * D_ : 0);
    const float* b1src = B1 + eb + (size_t)bkr * NTOT + n0 + bcf;
    const float* b3src = DUAL ? (B3 + eb + (size_t)bkr * NTOT + n0 + bcf) : A;
    const uint32_t adst = (uint32_t)(alr * (AF * 4) + alc * 4);
    const uint32_t bdst = (uint32_t)(bkr * (BF * 4) + bcf * 4);

    auto issue = [&](int c, int s) {
        uint32_t base = sb0 + (uint32_t)s * STAGE;
        const float* a = asrc + c * 32;
        #pragma unroll
        for (int j = 0; j < ACP; ++j) cp16(base + adst + j * 16, a + j * 4);
        const float* b = b1src + (size_t)c * 32 * NTOT;
        #pragma unroll
        for (int j = 0; j < 4; ++j) cp16(base + ABYTES + bdst + j * 16, b + j * 4);
        if (DUAL) {
            const float* b3 = b3src + (size_t)c * 32 * NTOT;
            #pragma unroll
            for (int j = 0; j < 4; ++j)
                cp16(base + ABYTES + BBYTES + bdst + j * 16, b3 + j * 4);
        }
        cp_commit();
    };

    // ---- accumulators: 4 m16 tiles x NT n8 tiles ----
    float acc1[4][NT][4];
    float acc3[DUAL ? 4 : 1][DUAL ? NT : 1][4];
    #pragma unroll
    for (int i = 0; i < 4; ++i)
        #pragma unroll
        for (int j = 0; j < NT; ++j)
            #pragma unroll
            for (int k = 0; k < 4; ++k) {
                acc1[i][j][k] = 0.f;
                if (DUAL) acc3[i][j][k] = 0.f;
            }

    const int g = lane >> 2, q = lane & 3;
    const int wr = (wid / WCN) * 64, wc = (wid % WCN) * (NT * 8);

    // ---- prologue: fill S-1 stages ----
    #pragma unroll
    for (int i = 0; i < S - 1; ++i) issue(i, i);
    cp_wait<S - 2>();
    __syncthreads();

    // ---- mainloop ----
    for (int c = 0; c < NCH; ++c) {
        const int s = c % S;
        if (c + S - 1 < NCH) issue(c + S - 1, (c + S - 1) % S);

        const float* As  = (const float*)(smem + (size_t)s * STAGE);
        const float* Bs1 = (const float*)(smem + (size_t)s * STAGE + ABYTES);
        const float* Bs3 = (const float*)(smem + (size_t)s * STAGE + ABYTES + BBYTES);

        #pragma unroll
        for (int ks = 0; ks < 4; ++ks) {
            const int kk = ks * 8;
            uint32_t af[4][4];
            #pragma unroll
            for (int mt = 0; mt < 4; ++mt) {
                const float* ap = As + (wr + 16 * mt + g) * AF + kk + q;
                af[mt][0] = __float_as_uint(ap[0]);
                af[mt][1] = __float_as_uint(ap[8 * AF]);
                af[mt][2] = __float_as_uint(ap[4]);
                af[mt][3] = __float_as_uint(ap[8 * AF + 4]);
            }
            #pragma unroll
            for (int nt = 0; nt < NT; ++nt) {
                const float* bp = Bs1 + (kk + q) * BF + wc + 8 * nt + g;
                uint32_t bf[2];
                bf[0] = rna_b(bp[0]);
                bf[1] = rna_b(bp[4 * BF]);
                #pragma unroll
                for (int mt = 0; mt < 4; ++mt)
                    mma8(acc1[mt][nt], af[mt], bf);
                if (DUAL) {
                    const float* bp3 = Bs3 + (kk + q) * BF + wc + 8 * nt + g;
                    uint32_t bf3[2];
                    bf3[0] = rna_b(bp3[0]);
                    bf3[1] = rna_b(bp3[4 * BF]);
                    #pragma unroll
                    for (int mt = 0; mt < 4; ++mt)
                        mma8(acc3[mt][nt], af[mt], bf3);
                }
            }
        }
        cp_wait<S - 2>();
        __syncthreads();
    }

    // ---- epilogue ----
    #pragma unroll
    for (int mt = 0; mt < 4; ++mt) {
        #pragma unroll
        for (int h = 0; h < 2; ++h) {
            const int grow = r0 + wr + 16 * mt + 8 * h + g;
            const bool valid = EXPERT ? (grow < nc) : true;
            if (!valid) continue;
            float* orow;
            if (MODE == 0)      orow = Out + (size_t)grow * HS_;
            else if (MODE == 1) orow = Out + (size_t)grow * D_;
            else if (MODE == 2) orow = Out + ((size_t)e * CAP_ + grow) * H_;
            else {
                int p = g_slot_pair[e * CAP_ + grow];
                orow = Out + (size_t)p * D_;
            }
            #pragma unroll
            for (int nt = 0; nt < NT; ++nt) {
                const int col = n0 + wc + 8 * nt + 2 * q;
                float v0 = acc1[mt][nt][2 * h];
                float v1 = acc1[mt][nt][2 * h + 1];
                if (DUAL) {
                    v0 = rna_f(silu_f(v0) * acc3[mt][nt][2 * h]);
                    v1 = rna_f(silu_f(v1) * acc3[mt][nt][2 * h + 1]);
                }
                float2 vv; vv.x = v0; vv.y = v1;
                *(float2*)(orow + col) = vv;
            }
        }
    }
}

// ---------------- combine: y = z + sum_k w_k * Obuf[pair] -------------------
__global__ __launch_bounds__(256) void combine_kernel(float* __restrict__ y)
{
    int t = blockIdx.x;
    int c4 = threadIdx.x;
    size_t off = (size_t)t * D_ + c4 * 4;
    float4 acc = *(float4*)(y + off);
    #pragma unroll
    for (int k = 0; k < TOPK_; ++k) {
        int p = t * TOPK_ + k;
        float w = g_pair_wc[p];
        float4 o = *(const float4*)(g_Obuf + (size_t)p * D_ + c4 * 4);
        acc.x = fmaf(w, o.x, acc.x);
        acc.y = fmaf(w, o.y, acc.y);
        acc.z = fmaf(w, o.z, acc.z);
        acc.w = fmaf(w, o.w, acc.w);
    }
    *(float4*)(y + off) = acc;
}

// ---------------- launch -----------------------------------------------------
extern "C" void kernel_launch(void* const* d_in, const int* in_sizes, int n_in,
                              void* d_out, int out_size)
{
    const float* x   = (const float*)d_in[0];
    const float* Wg  = (const float*)d_in[1];
    const float* W1  = (const float*)d_in[2];
    const float* W2  = (const float*)d_in[3];
    const float* W3  = (const float*)d_in[4];
    const float* Ws1 = (const float*)d_in[5];
    const float* Ws2 = (const float*)d_in[6];
    const float* Ws3 = (const float*)d_in[7];
    float* y = (float*)d_out;

    const int SMEM_DUAL   = 3 * (128*36*4 + 2 * 32*136*4);  // 159744
    const int SMEM_SINGLE = 4 * (256*36*4 + 1 * 32*136*4);  // 217088
    cudaFuncSetAttribute(gemm_mma<0>, cudaFuncAttributeMaxDynamicSharedMemorySize, SMEM_DUAL);
    cudaFuncSetAttribute(gemm_mma<1>, cudaFuncAttributeMaxDynamicSharedMemorySize, SMEM_SINGLE);
    cudaFuncSetAttribute(gemm_mma<2>, cudaFuncAttributeMaxDynamicSharedMemorySize, SMEM_DUAL);
    cudaFuncSetAttribute(gemm_mma<3>, cudaFuncAttributeMaxDynamicSharedMemorySize, SMEM_SINGLE);

    void *p_xr, *p_gs, *p_gbuf, *p_obuf;
    cudaGetSymbolAddress(&p_xr,   g_xr);
    cudaGetSymbolAddress(&p_gs,   g_Gs);
    cudaGetSymbolAddress(&p_gbuf, g_Gbuf);
    cudaGetSymbolAddress(&p_obuf, g_Obuf);

    // gating + dispatch
    gate_kernel<<<T_, 256>>>(x, Wg);
    zero_counts_kernel<<<1, 32>>>();
    dispatch_kernel<<<P_/256, 256>>>();

    // prepass: rna-round x only (16 MB; ~8us). Weights are rounded in-register.
    const int n4_x = T_*D_/4;
    round_copy<<<(n4_x + 255)/256, 256>>>((const float4*)x, (float4*)p_xr, n4_x);

    // shared expert (writes all of y via MODE 1)
    gemm_mma<0><<<dim3(HS_/128, T_/128), 256, SMEM_DUAL>>>(
        (const float*)p_xr, Ws1, Ws3, (float*)p_gs);
    gemm_mma<1><<<dim3(D_/128, T_/256), 256, SMEM_SINGLE>>>(
        (const float*)p_gs, Ws2, nullptr, y);

    // routed experts
    gemm_mma<2><<<dim3(H_/128, CAP_/128, E_), 256, SMEM_DUAL>>>(
        (const float*)p_xr, W1, W3, (float*)p_gbuf);
    gemm_mma<3><<<dim3(D_/128, CAP_/256, E_), 256, SMEM_SINGLE>>>(
        (const float*)p_gbuf, W2, nullptr, (float*)p_obuf);

    // deterministic combine
    combine_kernel<<<T_, 256>>>(y);
}

// round 11
// speedup vs baseline: 1.1514x; 1.1514x over previous
#include <cuda_runtime.h>
#include <math.h>
#include <stdint.h>

// Problem shapes (fixed by the dataset)
#define T_    4096
#define D_    1024
#define H_    512
#define E_    32
#define TOPK_ 4
#define CAP_  2048
#define HS_   1024
#define P_    (T_*TOPK_)

// ---------------- scratch (device globals) ----------------------------------
__device__ int   g_topk_idx[P_];
__device__ float g_topk_w[P_];
__device__ float g_pair_wc[P_];
__device__ int   g_counts[E_];
__device__ int   g_rows_token[E_*CAP_];
__device__ int   g_slot_pair[E_*CAP_];
__device__ __align__(256) float g_xr[(size_t)T_*D_];          // rna(x)
__device__ __align__(256) float g_Gs[(size_t)T_*HS_];         // shared hidden (rna)
__device__ __align__(256) float g_Gbuf[(size_t)E_*CAP_*H_];   // expert hidden (rna)
__device__ __align__(256) float g_Obuf[(size_t)P_*D_];        // per-pair outputs

// ---------------- helpers ----------------------------------------------------
__device__ __forceinline__ uint32_t smem_u32(const void* p) {
    uint32_t a;
    asm("{ .reg .u64 t; cvta.to.shared.u64 t, %1; cvt.u32.u64 %0, t; }"
        : "=r"(a) : "l"(p));
    return a;
}
__device__ __forceinline__ uint32_t rna_b(float v) {
    uint32_t o;
    asm("cvt.rna.tf32.f32 %0, %1;" : "=r"(o) : "f"(v));
    return o;
}
__device__ __forceinline__ float rna_f(float v) {
    return __uint_as_float(rna_b(v));
}
__device__ __forceinline__ void cp16(uint32_t saddr, const void* g) {
    asm volatile("cp.async.cg.shared.global [%0], [%1], 16;"
                 :: "r"(saddr), "l"(g) : "memory");
}
__device__ __forceinline__ void cp_commit() {
    asm volatile("cp.async.commit_group;" ::: "memory");
}
template<int N>
__device__ __forceinline__ void cp_wait() {
    asm volatile("cp.async.wait_group %0;" :: "n"(N) : "memory");
}
__device__ __forceinline__ void mma8(float* c, const uint32_t* a, const uint32_t* b) {
    asm volatile(
        "mma.sync.aligned.m16n8k8.row.col.f32.tf32.tf32.f32 "
        "{%0,%1,%2,%3}, {%4,%5,%6,%7}, {%8,%9}, {%0,%1,%2,%3};"
        : "+f"(c[0]), "+f"(c[1]), "+f"(c[2]), "+f"(c[3])
        : "r"(a[0]), "r"(a[1]), "r"(a[2]), "r"(a[3]), "r"(b[0]), "r"(b[1]));
}
__device__ __forceinline__ float silu_f(float h) {
    return h / (1.0f + expf(-h));
}

// ---------------- prepass: rna round-copy (x only; cheap) -------------------
__global__ __launch_bounds__(256) void round_copy(const float4* __restrict__ src,
                                                  float4* __restrict__ dst, int n4)
{
    int i = blockIdx.x * 256 + threadIdx.x;
    if (i < n4) {
        float4 v = src[i];
        v.x = rna_f(v.x); v.y = rna_f(v.y); v.z = rna_f(v.z); v.w = rna_f(v.w);
        dst[i] = v;
    }
}

// ---------------- gating -----------------------------------------------------
__global__ __launch_bounds__(256) void gate_kernel(const float* __restrict__ x,
                                                   const float* __restrict__ Wg)
{
    __shared__ float xs[D_];
    __shared__ float red[8][E_];
    __shared__ float probs[E_];
    int t = blockIdx.x, tid = threadIdx.x;
    ((float4*)xs)[tid] = ((const float4*)(x + (size_t)t * D_))[tid];
    __syncthreads();
    int e = tid & 31, seg = tid >> 5, k0 = seg * (D_/8);
    float acc = 0.f;
    #pragma unroll 8
    for (int k = 0; k < D_/8; ++k)
        acc = fmaf(xs[k0 + k], Wg[(size_t)(k0 + k) * E_ + e], acc);
    red[seg][e] = acc;
    __syncthreads();
    if (tid < E_) {
        float s = 0.f;
        #pragma unroll
        for (int i = 0; i < 8; ++i) s += red[i][tid];
        float m = s;
        #pragma unroll
        for (int o = 16; o > 0; o >>= 1) m = fmaxf(m, __shfl_xor_sync(0xffffffffu, m, o));
        float p = expf(s - m);
        float sum = p;
        #pragma unroll
        for (int o = 16; o > 0; o >>= 1) sum += __shfl_xor_sync(0xffffffffu, sum, o);
        probs[tid] = p / sum;
    }
    __syncthreads();
    if (tid == 0) {
        bool used[E_];
        #pragma unroll
        for (int i = 0; i < E_; ++i) used[i] = false;
        for (int k = 0; k < TOPK_; ++k) {
            float best = -1.f; int bi = 0;
            for (int i = 0; i < E_; ++i)
                if (!used[i] && probs[i] > best) { best = probs[i]; bi = i; }
            used[bi] = true;
            g_topk_idx[t * TOPK_ + k] = bi;
            g_topk_w  [t * TOPK_ + k] = best;
        }
    }
}

__global__ void zero_counts_kernel() {
    if (threadIdx.x < E_) g_counts[threadIdx.x] = 0;
}

__global__ void dispatch_kernel() {
    int p = blockIdx.x * blockDim.x + threadIdx.x;
    if (p >= P_) return;
    int e   = g_topk_idx[p];
    int tok = p >> 2;
    int pos = atomicAdd(&g_counts[e], 1);
    if (pos < CAP_) {
        int slot = e * CAP_ + pos;
        g_rows_token[slot] = tok;
        g_slot_pair[slot]  = p;
        g_pair_wc[p]       = g_topk_w[p];
    } else {
        g_pair_wc[p] = 0.0f;
    }
}

// ---------------- unified tf32 mma.sync GEMM (512 threads, 16 warps) --------
// DUAL  (MODE 0/2): CTA 128x128, warp 32x32 (4x4 grid), 4-stage
// SINGLE(MODE 1/3): CTA 256x128, warp 64x32 (4x4 grid), 4-stage
// One barrier per K32 chunk. A operands pre-rounded tf32; B (weights) rounded
// in-register per fragment.
template<int MODE>
__global__ void __launch_bounds__(512, 1)
gemm_mma(const float* __restrict__ A,
         const float* __restrict__ B1,
         const float* __restrict__ B3,
         float* __restrict__ Out)
{
    constexpr bool DUAL   = (MODE == 0 || MODE == 2);
    constexpr bool EXPERT = (MODE >= 2);
    constexpr int  KLEN   = (MODE == 3) ? H_ : ((MODE == 1) ? HS_ : D_);
    constexpr int  NTOT   = (MODE == 0) ? HS_ : ((MODE == 2) ? H_ : D_);
    constexpr int  NCH    = KLEN / 32;
    constexpr int  S      = 4;                       // pipeline stages
    constexpr int  MROWS  = DUAL ? 128 : 256;        // CTA M tile
    constexpr int  MT     = DUAL ? 2 : 4;            // m16 tiles per warp
    constexpr int  NT     = 4;                       // n8 tiles per warp (32 cols)
    constexpr int  AF     = 36;
    constexpr int  BF     = 136;
    constexpr int  ABYTES = MROWS * AF * 4;
    constexpr int  BBYTES = 32 * BF * 4;             // 17408
    constexpr int  STAGE  = ABYTES + (DUAL ? 2 : 1) * BBYTES;

    extern __shared__ char smem[];
    const uint32_t sb0 = smem_u32(smem);

    const int tid = threadIdx.x;
    const int wid = tid >> 5, lane = tid & 31;
    const int e   = EXPERT ? blockIdx.z : 0;
    const int nc  = EXPERT ? min(g_counts[e], CAP_) : (1 << 30);
    const int r0  = blockIdx.y * MROWS;
    if (EXPERT && r0 >= nc) return;
    const int n0  = blockIdx.x * 128;

    // ---- cp.async addressing ----
    // DUAL:   A 4 thr/row x 2 cp16 (128 rows); B 16 thr/row x 2 cp16
    // SINGLE: A 2 thr/row x 4 cp16 (256 rows); B 16 thr/row x 2 cp16
    const int alr = DUAL ? (tid >> 2) : (tid >> 1);
    const int alc = DUAL ? ((tid & 3) * 8) : ((tid & 1) * 16);
    constexpr int ACP = DUAL ? 2 : 4;
    const float* asrc;
    if (MODE == 2) {
        int gr  = min(r0 + alr, nc - 1);
        int tok = g_rows_token[e * CAP_ + gr];
        asrc = A + (size_t)tok * D_ + alc;
    } else if (MODE == 3) {
        asrc = A + ((size_t)e * CAP_ + r0 + alr) * H_ + alc;
    } else {
        asrc = A + (size_t)(r0 + alr) * KLEN + alc;
    }
    const int bkr = tid >> 4, bcf = (tid & 15) * 8;
    const size_t eb = (MODE == 2) ? (size_t)e * D_ * H_
                    : ((MODE == 3) ? (size_t)e * H_ * D_ : 0);
    const float* b1src = B1 + eb + (size_t)bkr * NTOT + n0 + bcf;
    const float* b3src = DUAL ? (B3 + eb + (size_t)bkr * NTOT + n0 + bcf) : A;
    const uint32_t adst = (uint32_t)(alr * (AF * 4) + alc * 4);
    const uint32_t bdst = (uint32_t)(bkr * (BF * 4) + bcf * 4);

    auto issue = [&](int c, int s) {
        uint32_t base = sb0 + (uint32_t)s * STAGE;
        const float* a = asrc + c * 32;
        #pragma unroll
        for (int j = 0; j < ACP; ++j) cp16(base + adst + j * 16, a + j * 4);
        const float* b = b1src + (size_t)c * 32 * NTOT;
        cp16(base + ABYTES + bdst,      b);
        cp16(base + ABYTES + bdst + 16, b + 4);
        if (DUAL) {
            const float* b3 = b3src + (size_t)c * 32 * NTOT;
            cp16(base + ABYTES + BBYTES + bdst,      b3);
            cp16(base + ABYTES + BBYTES + bdst + 16, b3 + 4);
        }
        cp_commit();
    };

    // ---- accumulators ----
    float acc1[MT][NT][4];
    float acc3[DUAL ? MT : 1][DUAL ? NT : 1][4];
    #pragma unroll
    for (int i = 0; i < MT; ++i)
        #pragma unroll
        for (int j = 0; j < NT; ++j)
            #pragma unroll
            for (int k = 0; k < 4; ++k) {
                acc1[i][j][k] = 0.f;
                if (DUAL) acc3[i][j][k] = 0.f;
            }

    const int g = lane >> 2, q = lane & 3;
    const int wr = (wid >> 2) * (MT * 16), wc = (wid & 3) * 32;  // 4x4 warp grid

    // ---- prologue: fill S-1 stages ----
    #pragma unroll
    for (int i = 0; i < S - 1; ++i) issue(i, i);
    cp_wait<S - 2>();
    __syncthreads();

    // ---- mainloop: one barrier per chunk ----
    for (int c = 0; c < NCH; ++c) {
        const int s = c % S;
        if (c + S - 1 < NCH) issue(c + S - 1, (c + S - 1) % S);

        const float* As  = (const float*)(smem + (size_t)s * STAGE);
        const float* Bs1 = (const float*)(smem + (size_t)s * STAGE + ABYTES);
        const float* Bs3 = (const float*)(smem + (size_t)s * STAGE + ABYTES + BBYTES);

        #pragma unroll
        for (int ks = 0; ks < 4; ++ks) {
            const int kk = ks * 8;
            uint32_t af[MT][4];
            #pragma unroll
            for (int mt = 0; mt < MT; ++mt) {
                const float* ap = As + (wr + 16 * mt + g) * AF + kk + q;
                af[mt][0] = __float_as_uint(ap[0]);
                af[mt][1] = __float_as_uint(ap[8 * AF]);
                af[mt][2] = __float_as_uint(ap[4]);
                af[mt][3] = __float_as_uint(ap[8 * AF + 4]);
            }
            #pragma unroll
            for (int nt = 0; nt < NT; ++nt) {
                const float* bp = Bs1 + (kk + q) * BF + wc + 8 * nt + g;
                uint32_t bf[2];
                bf[0] = rna_b(bp[0]);
                bf[1] = rna_b(bp[4 * BF]);
                #pragma unroll
                for (int mt = 0; mt < MT; ++mt)
                    mma8(acc1[mt][nt], af[mt], bf);
                if (DUAL) {
                    const float* bp3 = Bs3 + (kk + q) * BF + wc + 8 * nt + g;
                    uint32_t bf3[2];
                    bf3[0] = rna_b(bp3[0]);
                    bf3[1] = rna_b(bp3[4 * BF]);
                    #pragma unroll
                    for (int mt = 0; mt < MT; ++mt)
                        mma8(acc3[mt][nt], af[mt], bf3);
                }
            }
        }
        cp_wait<S - 2>();
        __syncthreads();
    }

    // ---- epilogue ----
    #pragma unroll
    for (int mt = 0; mt < MT; ++mt) {
        #pragma unroll
        for (int h = 0; h < 2; ++h) {
            const int grow = r0 + wr + 16 * mt + 8 * h + g;
            const bool valid = EXPERT ? (grow < nc) : true;
            if (!valid) continue;
            float* orow;
            if (MODE == 0)      orow = Out + (size_t)grow * HS_;
            else if (MODE == 1) orow = Out + (size_t)grow * D_;
            else if (MODE == 2) orow = Out + ((size_t)e * CAP_ + grow) * H_;
            else {
                int p = g_slot_pair[e * CAP_ + grow];
                orow = Out + (size_t)p * D_;
            }
            #pragma unroll
            for (int nt = 0; nt < NT; ++nt) {
                const int col = n0 + wc + 8 * nt + 2 * q;
                float v0 = acc1[mt][nt][2 * h];
                float v1 = acc1[mt][nt][2 * h + 1];
                if (DUAL) {
                    v0 = rna_f(silu_f(v0) * acc3[mt][nt][2 * h]);
                    v1 = rna_f(silu_f(v1) * acc3[mt][nt][2 * h + 1]);
                }
                float2 vv; vv.x = v0; vv.y = v1;
                *(float2*)(orow + col) = vv;
            }
        }
    }
}

// ---------------- combine: y = z + sum_k w_k * Obuf[pair] -------------------
__global__ __launch_bounds__(256) void combine_kernel(float* __restrict__ y)
{
    int t = blockIdx.x;
    int c4 = threadIdx.x;
    size_t off = (size_t)t * D_ + c4 * 4;
    float4 acc = *(float4*)(y + off);
    #pragma unroll
    for (int k = 0; k < TOPK_; ++k) {
        int p = t * TOPK_ + k;
        float w = g_pair_wc[p];
        float4 o = *(const float4*)(g_Obuf + (size_t)p * D_ + c4 * 4);
        acc.x = fmaf(w, o.x, acc.x);
        acc.y = fmaf(w, o.y, acc.y);
        acc.z = fmaf(w, o.z, acc.z);
        acc.w = fmaf(w, o.w, acc.w);
    }
    *(float4*)(y + off) = acc;
}

// ---------------- launch -----------------------------------------------------
extern "C" void kernel_launch(void* const* d_in, const int* in_sizes, int n_in,
                              void* d_out, int out_size)
{
    const float* x   = (const float*)d_in[0];
    const float* Wg  = (const float*)d_in[1];
    const float* W1  = (const float*)d_in[2];
    const float* W2  = (const float*)d_in[3];
    const float* W3  = (const float*)d_in[4];
    const float* Ws1 = (const float*)d_in[5];
    const float* Ws2 = (const float*)d_in[6];
    const float* Ws3 = (const float*)d_in[7];
    float* y = (float*)d_out;

    const int SMEM_DUAL   = 4 * (128*36*4 + 2 * 32*136*4);  // 212992
    const int SMEM_SINGLE = 4 * (256*36*4 + 1 * 32*136*4);  // 217088
    cudaFuncSetAttribute(gemm_mma<0>, cudaFuncAttributeMaxDynamicSharedMemorySize, SMEM_DUAL);
    cudaFuncSetAttribute(gemm_mma<1>, cudaFuncAttributeMaxDynamicSharedMemorySize, SMEM_SINGLE);
    cudaFuncSetAttribute(gemm_mma<2>, cudaFuncAttributeMaxDynamicSharedMemorySize, SMEM_DUAL);
    cudaFuncSetAttribute(gemm_mma<3>, cudaFuncAttributeMaxDynamicSharedMemorySize, SMEM_SINGLE);

    void *p_xr, *p_gs, *p_gbuf, *p_obuf;
    cudaGetSymbolAddress(&p_xr,   g_xr);
    cudaGetSymbolAddress(&p_gs,   g_Gs);
    cudaGetSymbolAddress(&p_gbuf, g_Gbuf);
    cudaGetSymbolAddress(&p_obuf, g_Obuf);

    // gating + dispatch
    gate_kernel<<<T_, 256>>>(x, Wg);
    zero_counts_kernel<<<1, 32>>>();
    dispatch_kernel<<<P_/256, 256>>>();

    // prepass: rna-round x only (16 MB; ~8us). Weights are rounded in-register.
    const int n4_x = T_*D_/4;
    round_copy<<<(n4_x + 255)/256, 256>>>((const float4*)x, (float4*)p_xr, n4_x);

    // shared expert (writes all of y via MODE 1)
    gemm_mma<0><<<dim3(HS_/128, T_/128), 512, SMEM_DUAL>>>(
        (const float*)p_xr, Ws1, Ws3, (float*)p_gs);
    gemm_mma<1><<<dim3(D_/128, T_/256), 512, SMEM_SINGLE>>>(
        (const float*)p_gs, Ws2, nullptr, y);

    // routed experts
    gemm_mma<2><<<dim3(H_/128, CAP_/128, E_), 512, SMEM_DUAL>>>(
        (const float*)p_xr, W1, W3, (float*)p_gbuf);
    gemm_mma<3><<<dim3(D_/128, CAP_/256, E_), 512, SMEM_SINGLE>>>(
        (const float*)p_gbuf, W2, nullptr, (float*)p_obuf);

    // deterministic combine
    combine_kernel<<<T_, 256>>>(y);
}

// round 13
// speedup vs baseline: 1.2764x; 1.1086x over previous
#include <cuda_runtime.h>
#include <math.h>
#include <stdint.h>

// Problem shapes (fixed by the dataset)
#define T_    4096
#define D_    1024
#define H_    512
#define E_    32
#define TOPK_ 4
#define CAP_  2048
#define HS_   1024
#define P_    (T_*TOPK_)

// ---------------- scratch (device globals) ----------------------------------
__device__ int   g_topk_idx[P_];
__device__ float g_topk_w[P_];
__device__ float g_pair_wc[P_];
__device__ int   g_counts[E_];
__device__ int   g_rows_token[E_*CAP_];
__device__ int   g_slot_pair[E_*CAP_];
__device__ __align__(256) float g_Gs[(size_t)T_*HS_];         // shared hidden
__device__ __align__(256) float g_Gbuf[(size_t)E_*CAP_*H_];   // expert hidden
__device__ __align__(256) float g_Obuf[(size_t)P_*D_];        // per-pair outputs

// ---------------- helpers ----------------------------------------------------
__device__ __forceinline__ uint32_t smem_u32(const void* p) {
    uint32_t a;
    asm("{ .reg .u64 t; cvta.to.shared.u64 t, %1; cvt.u32.u64 %0, t; }"
        : "=r"(a) : "l"(p));
    return a;
}
// pack two f32 into f16x2: result.lo = lo, result.hi = hi (cvt.rn)
__device__ __forceinline__ uint32_t pack_h2(float hi, float lo) {
    uint32_t d;
    asm("cvt.rn.f16x2.f32 %0, %1, %2;" : "=r"(d) : "f"(hi), "f"(lo));
    return d;
}
__device__ __forceinline__ void cp16(uint32_t saddr, const void* g) {
    asm volatile("cp.async.cg.shared.global [%0], [%1], 16;"
                 :: "r"(saddr), "l"(g) : "memory");
}
__device__ __forceinline__ void cp_commit() {
    asm volatile("cp.async.commit_group;" ::: "memory");
}
template<int N>
__device__ __forceinline__ void cp_wait() {
    asm volatile("cp.async.wait_group %0;" :: "n"(N) : "memory");
}
// fp16 MMA m16n8k16, fp32 accumulate
__device__ __forceinline__ void mma16(float* c, const uint32_t* a, const uint32_t* b) {
    asm volatile(
        "mma.sync.aligned.m16n8k16.row.col.f32.f16.f16.f32 "
        "{%0,%1,%2,%3}, {%4,%5,%6,%7}, {%8,%9}, {%0,%1,%2,%3};"
        : "+f"(c[0]), "+f"(c[1]), "+f"(c[2]), "+f"(c[3])
        : "r"(a[0]), "r"(a[1]), "r"(a[2]), "r"(a[3]), "r"(b[0]), "r"(b[1]));
}
__device__ __forceinline__ float silu_f(float h) {
    return h / (1.0f + expf(-h));
}

// ---------------- gating -----------------------------------------------------
__global__ __launch_bounds__(256) void gate_kernel(const float* __restrict__ x,
                                                   const float* __restrict__ Wg)
{
    __shared__ float xs[D_];
    __shared__ float red[8][E_];
    __shared__ float probs[E_];
    int t = blockIdx.x, tid = threadIdx.x;
    ((float4*)xs)[tid] = ((const float4*)(x + (size_t)t * D_))[tid];
    __syncthreads();
    int e = tid & 31, seg = tid >> 5, k0 = seg * (D_/8);
    float acc = 0.f;
    #pragma unroll 8
    for (int k = 0; k < D_/8; ++k)
        acc = fmaf(xs[k0 + k], Wg[(size_t)(k0 + k) * E_ + e], acc);
    red[seg][e] = acc;
    __syncthreads();
    if (tid < E_) {
        float s = 0.f;
        #pragma unroll
        for (int i = 0; i < 8; ++i) s += red[i][tid];
        float m = s;
        #pragma unroll
        for (int o = 16; o > 0; o >>= 1) m = fmaxf(m, __shfl_xor_sync(0xffffffffu, m, o));
        float p = expf(s - m);
        float sum = p;
        #pragma unroll
        for (int o = 16; o > 0; o >>= 1) sum += __shfl_xor_sync(0xffffffffu, sum, o);
        probs[tid] = p / sum;
    }
    __syncthreads();
    if (tid == 0) {
        bool used[E_];
        #pragma unroll
        for (int i = 0; i < E_; ++i) used[i] = false;
        for (int k = 0; k < TOPK_; ++k) {
            float best = -1.f; int bi = 0;
            for (int i = 0; i < E_; ++i)
                if (!used[i] && probs[i] > best) { best = probs[i]; bi = i; }
            used[bi] = true;
            g_topk_idx[t * TOPK_ + k] = bi;
            g_topk_w  [t * TOPK_ + k] = best;
        }
    }
}

__global__ void zero_counts_kernel() {
    if (threadIdx.x < E_) g_counts[threadIdx.x] = 0;
}

__global__ void dispatch_kernel() {
    int p = blockIdx.x * blockDim.x + threadIdx.x;
    if (p >= P_) return;
    int e   = g_topk_idx[p];
    int tok = p >> 2;
    int pos = atomicAdd(&g_counts[e], 1);
    if (pos < CAP_) {
        int slot = e * CAP_ + pos;
        g_rows_token[slot] = tok;
        g_slot_pair[slot]  = p;
        g_pair_wc[p]       = g_topk_w[p];
    } else {
        g_pair_wc[p] = 0.0f;
    }
}

// ---------------- unified fp16 mma.sync GEMM (512 threads, 16 warps) --------
// MODE 0: Gs   = silu(x@Ws1)*(x@Ws3)   dual    MODE 1: y    = Gs@Ws2
// MODE 2: Gbuf = silu(xg@W1)*(xg@W3)   dual    MODE 3: Obuf = Gbuf@W2
// CTA tile 128x128, warp tile 32x32 (4x4 grid). K-chunk 32 (2 x k16 MMA
// slices); stages: dual 3, single 4. fp32 in smem (same cp.async paths);
// fragments converted to f16x2 in registers (cvt.rn = the rounding step).
template<int MODE>
__global__ void __launch_bounds__(512, 1)
gemm_mma(const float* __restrict__ A,
         const float* __restrict__ B1,
         const float* __restrict__ B3,
         float* __restrict__ Out)
{
    constexpr bool DUAL   = (MODE == 0 || MODE == 2);
    constexpr bool EXPERT = (MODE >= 2);
    constexpr int  KLEN   = (MODE == 3) ? H_ : ((MODE == 1) ? HS_ : D_);
    constexpr int  NTOT   = (MODE == 0) ? HS_ : ((MODE == 2) ? H_ : D_);
    constexpr int  NCH    = KLEN / 32;
    constexpr int  S      = DUAL ? 3 : 4;            // pipeline stages
    constexpr int  NT     = 4;                       // n8 tiles per warp
    constexpr int  AF     = 36;                      // A smem row stride (floats)
    constexpr int  BF     = 132;                     // B smem row stride (floats)
    constexpr int  ABYTES = 128 * AF * 4;            // 18432
    constexpr int  BBYTES = 32 * BF * 4;             // 16896
    constexpr int  STAGE  = ABYTES + (DUAL ? 2 : 1) * BBYTES;

    extern __shared__ char smem[];
    const uint32_t sb0 = smem_u32(smem);

    const int tid = threadIdx.x;
    const int wid = tid >> 5, lane = tid & 31;
    const int e   = EXPERT ? blockIdx.z : 0;
    const int nc  = EXPERT ? min(g_counts[e], CAP_) : (1 << 30);
    const int r0  = blockIdx.y * 128;
    if (EXPERT && r0 >= nc) return;
    const int n0  = blockIdx.x * 128;

    // ---- cp.async addressing: A 4 thr/row x 2 cp16; B 16 thr/row x 2 cp16 --
    const int alr = tid >> 2, alc = (tid & 3) * 8;
    const float* asrc;
    if (MODE == 2) {
        int gr  = min(r0 + alr, nc - 1);
        int tok = g_rows_token[e * CAP_ + gr];
        asrc = A + (size_t)tok * D_ + alc;
    } else if (MODE == 3) {
        asrc = A + ((size_t)e * CAP_ + r0 + alr) * H_ + alc;
    } else {
        asrc = A + (size_t)(r0 + alr) * KLEN + alc;
    }
    const int bkr = tid >> 4, bcf = (tid & 15) * 8;
    const size_t eb = (MODE == 2) ? (size_t)e * D_ * H_
                    : ((MODE == 3) ? (size_t)e * H_ * D_ : 0);
    const float* b1src = B1 + eb + (size_t)bkr * NTOT + n0 + bcf;
    const float* b3src = DUAL ? (B3 + eb + (size_t)bkr * NTOT + n0 + bcf) : A;
    const uint32_t adst = (uint32_t)(alr * (AF * 4) + alc * 4);
    const uint32_t bdst = (uint32_t)(bkr * (BF * 4) + bcf * 4);

    auto issue = [&](int c, int s) {
        uint32_t base = sb0 + (uint32_t)s * STAGE;
        const float* a = asrc + c * 32;
        cp16(base + adst,      a);
        cp16(base + adst + 16, a + 4);
        const float* b = b1src + (size_t)c * 32 * NTOT;
        cp16(base + ABYTES + bdst,      b);
        cp16(base + ABYTES + bdst + 16, b + 4);
        if (DUAL) {
            const float* b3 = b3src + (size_t)c * 32 * NTOT;
            cp16(base + ABYTES + BBYTES + bdst,      b3);
            cp16(base + ABYTES + BBYTES + bdst + 16, b3 + 4);
        }
        cp_commit();
    };

    // ---- accumulators ----
    float acc1[2][NT][4];
    float acc3[DUAL ? 2 : 1][DUAL ? NT : 1][4];
    #pragma unroll
    for (int i = 0; i < 2; ++i)
        #pragma unroll
        for (int j = 0; j < NT; ++j)
            #pragma unroll
            for (int k = 0; k < 4; ++k) {
                acc1[i][j][k] = 0.f;
                if (DUAL) acc3[i][j][k] = 0.f;
            }

    const int g = lane >> 2, q = lane & 3;
    const int wr = (wid >> 2) * 32, wc = (wid & 3) * 32;   // 4x4 warp grid

    // ---- prologue: fill S-1 stages ----
    #pragma unroll
    for (int i = 0; i < S - 1; ++i) issue(i, i);
    cp_wait<S - 2>();
    __syncthreads();

    // ---- mainloop: one barrier per chunk, 2 x k16 MMA slices ----
    for (int c = 0; c < NCH; ++c) {
        const int s = c % S;
        if (c + S - 1 < NCH) issue(c + S - 1, (c + S - 1) % S);

        const float* As  = (const float*)(smem + (size_t)s * STAGE);
        const float* Bs1 = (const float*)(smem + (size_t)s * STAGE + ABYTES);
        const float* Bs3 = (const float*)(smem + (size_t)s * STAGE + ABYTES + BBYTES);

        #pragma unroll
        for (int ks = 0; ks < 2; ++ks) {
            const int kk = ks * 16;
            uint32_t af[2][4];
            #pragma unroll
            for (int mt = 0; mt < 2; ++mt) {
                const float* ap = As + (wr + 16 * mt + g) * AF + kk + 2 * q;
                float2 v0 = *(const float2*)(ap);               // row g,   k 2q
                float2 v1 = *(const float2*)(ap + 8 * AF);      // row g+8, k 2q
                float2 v2 = *(const float2*)(ap + 8);           // row g,   k 2q+8
                float2 v3 = *(const float2*)(ap + 8 * AF + 8);  // row g+8, k 2q+8
                af[mt][0] = pack_h2(v0.y, v0.x);
                af[mt][1] = pack_h2(v1.y, v1.x);
                af[mt][2] = pack_h2(v2.y, v2.x);
                af[mt][3] = pack_h2(v3.y, v3.x);
            }
            #pragma unroll
            for (int nt = 0; nt < NT; ++nt) {
                const float* bp = Bs1 + (kk + 2 * q) * BF + wc + 8 * nt + g;
                uint32_t bf[2];
                bf[0] = pack_h2(bp[BF], bp[0]);            // k 2q+1, 2q
                bf[1] = pack_h2(bp[9 * BF], bp[8 * BF]);   // k 2q+9, 2q+8
                mma16(acc1[0][nt], af[0], bf);
                mma16(acc1[1][nt], af[1], bf);
                if (DUAL) {
                    const float* bp3 = Bs3 + (kk + 2 * q) * BF + wc + 8 * nt + g;
                    uint32_t bf3[2];
                    bf3[0] = pack_h2(bp3[BF], bp3[0]);
                    bf3[1] = pack_h2(bp3[9 * BF], bp3[8 * BF]);
                    mma16(acc3[0][nt], af[0], bf3);
                    mma16(acc3[1][nt], af[1], bf3);
                }
            }
        }
        cp_wait<S - 2>();
        __syncthreads();
    }

    // ---- epilogue ----
    #pragma unroll
    for (int mt = 0; mt < 2; ++mt) {
        #pragma unroll
        for (int h = 0; h < 2; ++h) {
            const int grow = r0 + wr + 16 * mt + 8 * h + g;
            const bool valid = EXPERT ? (grow < nc) : true;
            if (!valid) continue;
            float* orow;
            if (MODE == 0)      orow = Out + (size_t)grow * HS_;
            else if (MODE == 1) orow = Out + (size_t)grow * D_;
            else if (MODE == 2) orow = Out + ((size_t)e * CAP_ + grow) * H_;
            else {
                int p = g_slot_pair[e * CAP_ + grow];
                orow = Out + (size_t)p * D_;
            }
            #pragma unroll
            for (int nt = 0; nt < NT; ++nt) {
                const int col = n0 + wc + 8 * nt + 2 * q;
                float v0 = acc1[mt][nt][2 * h];
                float v1 = acc1[mt][nt][2 * h + 1];
                if (DUAL) {
                    v0 = silu_f(v0) * acc3[mt][nt][2 * h];
                    v1 = silu_f(v1) * acc3[mt][nt][2 * h + 1];
                }
                float2 vv; vv.x = v0; vv.y = v1;
                *(float2*)(orow + col) = vv;
            }
        }
    }
}

// ---------------- combine: y = z + sum_k w_k * Obuf[pair] -------------------
__global__ __launch_bounds__(256) void combine_kernel(float* __restrict__ y)
{
    int t = blockIdx.x;
    int c4 = threadIdx.x;
    size_t off = (size_t)t * D_ + c4 * 4;
    float4 acc = *(float4*)(y + off);
    #pragma unroll
    for (int k = 0; k < TOPK_; ++k) {
        int p = t * TOPK_ + k;
        float w = g_pair_wc[p];
        float4 o = *(const float4*)(g_Obuf + (size_t)p * D_ + c4 * 4);
        acc.x = fmaf(w, o.x, acc.x);
        acc.y = fmaf(w, o.y, acc.y);
        acc.z = fmaf(w, o.z, acc.z);
        acc.w = fmaf(w, o.w, acc.w);
    }
    *(float4*)(y + off) = acc;
}

// ---------------- launch -----------------------------------------------------
extern "C" void kernel_launch(void* const* d_in, const int* in_sizes, int n_in,
                              void* d_out, int out_size)
{
    const float* x   = (const float*)d_in[0];
    const float* Wg  = (const float*)d_in[1];
    const float* W1  = (const float*)d_in[2];
    const float* W2  = (const float*)d_in[3];
    const float* W3  = (const float*)d_in[4];
    const float* Ws1 = (const float*)d_in[5];
    const float* Ws2 = (const float*)d_in[6];
    const float* Ws3 = (const float*)d_in[7];
    float* y = (float*)d_out;

    const int SMEM_DUAL   = 3 * (128*36*4 + 2 * 32*132*4);  // 156672
    const int SMEM_SINGLE = 4 * (128*36*4 + 1 * 32*132*4);  // 141312
    cudaFuncSetAttribute(gemm_mma<0>, cudaFuncAttributeMaxDynamicSharedMemorySize, SMEM_DUAL);
    cudaFuncSetAttribute(gemm_mma<1>, cudaFuncAttributeMaxDynamicSharedMemorySize, SMEM_SINGLE);
    cudaFuncSetAttribute(gemm_mma<2>, cudaFuncAttributeMaxDynamicSharedMemorySize, SMEM_DUAL);
    cudaFuncSetAttribute(gemm_mma<3>, cudaFuncAttributeMaxDynamicSharedMemorySize, SMEM_SINGLE);

    void *p_gs, *p_gbuf, *p_obuf;
    cudaGetSymbolAddress(&p_gs,   g_Gs);
    cudaGetSymbolAddress(&p_gbuf, g_Gbuf);
    cudaGetSymbolAddress(&p_obuf, g_Obuf);

    // gating + dispatch
    gate_kernel<<<T_, 256>>>(x, Wg);
    zero_counts_kernel<<<1, 32>>>();
    dispatch_kernel<<<P_/256, 256>>>();

    // shared expert (writes all of y via MODE 1)
    gemm_mma<0><<<dim3(HS_/128, T_/128), 512, SMEM_DUAL>>>(x, Ws1, Ws3, (float*)p_gs);
    gemm_mma<1><<<dim3(D_/128, T_/128), 512, SMEM_SINGLE>>>(
        (const float*)p_gs, Ws2, nullptr, y);

    // routed experts
    gemm_mma<2><<<dim3(H_/128, CAP_/128, E_), 512, SMEM_DUAL>>>(x, W1, W3, (float*)p_gbuf);
    gemm_mma<3><<<dim3(D_/128, CAP_/128, E_), 512, SMEM_SINGLE>>>(
        (const float*)p_gbuf, W2, nullptr, (float*)p_obuf);

    // deterministic combine
    combine_kernel<<<T_, 256>>>(y);
}

// round 14
// speedup vs baseline: 2.1528x; 1.6866x over previous
#include <cuda_runtime.h>
#include <cuda_fp16.h>
#include <math.h>
#include <stdint.h>

// Problem shapes (fixed by the dataset)
#define T_    4096
#define D_    1024
#define H_    512
#define E_    32
#define TOPK_ 4
#define CAP_  2048
#define HS_   1024
#define P_    (T_*TOPK_)

// ---------------- scratch (device globals) ----------------------------------
__device__ int   g_topk_idx[P_];
__device__ float g_topk_w[P_];
__device__ float g_pair_wc[P_];
__device__ int   g_counts[E_];
__device__ int   g_rows_token[E_*CAP_];
__device__ int   g_slot_pair[E_*CAP_];
// fp16 copies of inputs
__device__ __align__(256) __half g_xh[(size_t)T_*D_];
__device__ __align__(256) __half g_W1h[(size_t)E_*D_*H_];
__device__ __align__(256) __half g_W3h[(size_t)E_*D_*H_];
__device__ __align__(256) __half g_W2h[(size_t)E_*H_*D_];
__device__ __align__(256) __half g_Ws1h[(size_t)D_*HS_];
__device__ __align__(256) __half g_Ws3h[(size_t)D_*HS_];
__device__ __align__(256) __half g_Ws2h[(size_t)HS_*D_];
// intermediates
__device__ __align__(256) __half g_Gsh[(size_t)T_*HS_];      // shared hidden
__device__ __align__(256) __half g_Gbufh[(size_t)E_*CAP_*H_];// expert hidden
__device__ __align__(256) float  g_Obuf[(size_t)P_*D_];      // per-pair outputs

// ---------------- helpers ----------------------------------------------------
__device__ __forceinline__ uint32_t smem_u32(const void* p) {
    uint32_t a;
    asm("{ .reg .u64 t; cvta.to.shared.u64 t, %1; cvt.u32.u64 %0, t; }"
        : "=r"(a) : "l"(p));
    return a;
}
__device__ __forceinline__ uint32_t pack_h2(float hi, float lo) {
    uint32_t d;
    asm("cvt.rn.f16x2.f32 %0, %1, %2;" : "=r"(d) : "f"(hi), "f"(lo));
    return d;
}
__device__ __forceinline__ void cp16(uint32_t saddr, const void* g) {
    asm volatile("cp.async.cg.shared.global [%0], [%1], 16;"
                 :: "r"(saddr), "l"(g) : "memory");
}
__device__ __forceinline__ void cp_commit() {
    asm volatile("cp.async.commit_group;" ::: "memory");
}
template<int N>
__device__ __forceinline__ void cp_wait() {
    asm volatile("cp.async.wait_group %0;" :: "n"(N) : "memory");
}
__device__ __forceinline__ void ldsm_x4(uint32_t* r, uint32_t a) {
    asm volatile("ldmatrix.sync.aligned.m8n8.x4.shared.b16 {%0,%1,%2,%3}, [%4];"
        : "=r"(r[0]), "=r"(r[1]), "=r"(r[2]), "=r"(r[3]) : "r"(a));
}
__device__ __forceinline__ void ldsm_x4t(uint32_t* r, uint32_t a) {
    asm volatile("ldmatrix.sync.aligned.m8n8.x4.trans.shared.b16 {%0,%1,%2,%3}, [%4];"
        : "=r"(r[0]), "=r"(r[1]), "=r"(r[2]), "=r"(r[3]) : "r"(a));
}
__device__ __forceinline__ void mma16(float* c, const uint32_t* a, const uint32_t* b) {
    asm volatile(
        "mma.sync.aligned.m16n8k16.row.col.f32.f16.f16.f32 "
        "{%0,%1,%2,%3}, {%4,%5,%6,%7}, {%8,%9}, {%0,%1,%2,%3};"
        : "+f"(c[0]), "+f"(c[1]), "+f"(c[2]), "+f"(c[3])
        : "r"(a[0]), "r"(a[1]), "r"(a[2]), "r"(a[3]), "r"(b[0]), "r"(b[1]));
}
__device__ __forceinline__ float silu_f(float h) {
    return h / (1.0f + expf(-h));
}

// ---------------- prepass: fp32 -> fp16 convert ------------------------------
__global__ __launch_bounds__(256) void f32_to_f16(const float4* __restrict__ src,
                                                  uint2* __restrict__ dst, int n4)
{
    int i = blockIdx.x * 256 + threadIdx.x;
    if (i < n4) {
        float4 v = src[i];
        uint2 o;
        o.x = pack_h2(v.y, v.x);
        o.y = pack_h2(v.w, v.z);
        dst[i] = o;
    }
}

// ---------------- gating -----------------------------------------------------
__global__ __launch_bounds__(256) void gate_kernel(const float* __restrict__ x,
                                                   const float* __restrict__ Wg)
{
    __shared__ float xs[D_];
    __shared__ float red[8][E_];
    __shared__ float probs[E_];
    int t = blockIdx.x, tid = threadIdx.x;
    ((float4*)xs)[tid] = ((const float4*)(x + (size_t)t * D_))[tid];
    __syncthreads();
    int e = tid & 31, seg = tid >> 5, k0 = seg * (D_/8);
    float acc = 0.f;
    #pragma unroll 8
    for (int k = 0; k < D_/8; ++k)
        acc = fmaf(xs[k0 + k], Wg[(size_t)(k0 + k) * E_ + e], acc);
    red[seg][e] = acc;
    __syncthreads();
    if (tid < E_) {
        float s = 0.f;
        #pragma unroll
        for (int i = 0; i < 8; ++i) s += red[i][tid];
        float m = s;
        #pragma unroll
        for (int o = 16; o > 0; o >>= 1) m = fmaxf(m, __shfl_xor_sync(0xffffffffu, m, o));
        float p = expf(s - m);
        float sum = p;
        #pragma unroll
        for (int o = 16; o > 0; o >>= 1) sum += __shfl_xor_sync(0xffffffffu, sum, o);
        probs[tid] = p / sum;
    }
    __syncthreads();
    if (tid == 0) {
        bool used[E_];
        #pragma unroll
        for (int i = 0; i < E_; ++i) used[i] = false;
        for (int k = 0; k < TOPK_; ++k) {
            float best = -1.f; int bi = 0;
            for (int i = 0; i < E_; ++i)
                if (!used[i] && probs[i] > best) { best = probs[i]; bi = i; }
            used[bi] = true;
            g_topk_idx[t * TOPK_ + k] = bi;
            g_topk_w  [t * TOPK_ + k] = best;
        }
    }
}

__global__ void zero_counts_kernel() {
    if (threadIdx.x < E_) g_counts[threadIdx.x] = 0;
}

__global__ void dispatch_kernel() {
    int p = blockIdx.x * blockDim.x + threadIdx.x;
    if (p >= P_) return;
    int e   = g_topk_idx[p];
    int tok = p >> 2;
    int pos = atomicAdd(&g_counts[e], 1);
    if (pos < CAP_) {
        int slot = e * CAP_ + pos;
        g_rows_token[slot] = tok;
        g_slot_pair[slot]  = p;
        g_pair_wc[p]       = g_topk_w[p];
    } else {
        g_pair_wc[p] = 0.0f;
    }
}

// ---------------- unified fp16 ldmatrix GEMM (512 threads, 16 warps) --------
// MODE 0: Gsh   = h(silu(x@Ws1)*(x@Ws3))  dual    MODE 1: y    = Gsh@Ws2
// MODE 2: Gbufh = h(silu(xg@W1)*(xg@W3))  dual    MODE 3: Obuf = Gbufh@W2
// CTA 128x128, warp 32x32 (4x4 grid). fp16 smem; K-chunk 32 (2 x k16 slices);
// stages dual 3 / single 4. A row stride 80B, B row stride 272B (both odd
// multiples of 16B -> ldmatrix conflict-free). No in-loop cvt.
template<int MODE>
__global__ void __launch_bounds__(512, 1)
gemm_mma(const __half* __restrict__ A,
         const __half* __restrict__ B1,
         const __half* __restrict__ B3,
         void* __restrict__ OutV)
{
    constexpr bool DUAL   = (MODE == 0 || MODE == 2);
    constexpr bool EXPERT = (MODE >= 2);
    constexpr int  KLEN   = (MODE == 3) ? H_ : ((MODE == 1) ? HS_ : D_);
    constexpr int  NTOT   = (MODE == 0) ? HS_ : ((MODE == 2) ? H_ : D_);
    constexpr int  NCH    = KLEN / 32;
    constexpr int  S      = DUAL ? 3 : 4;            // pipeline stages
    constexpr int  NT     = 4;                       // n8 tiles per warp
    constexpr int  ARB    = 80;                      // A smem row bytes (40 halves)
    constexpr int  BRB    = 272;                     // B smem row bytes (136 halves)
    constexpr int  ABYTES = 128 * ARB;               // 10240
    constexpr int  BBYTES = 32 * BRB;                // 8704
    constexpr int  STAGE  = ABYTES + (DUAL ? 2 : 1) * BBYTES;

    extern __shared__ char smem[];
    const uint32_t sb0 = smem_u32(smem);

    const int tid = threadIdx.x;
    const int wid = tid >> 5, lane = tid & 31;
    const int e   = EXPERT ? blockIdx.z : 0;
    const int nc  = EXPERT ? min(g_counts[e], CAP_) : (1 << 30);
    const int r0  = blockIdx.y * 128;
    if (EXPERT && r0 >= nc) return;
    const int n0  = blockIdx.x * 128;

    // ---- cp.async addressing: A 4 thr/row x 1 cp16; B 16 thr/row x 1 cp16 --
    const int alr = tid >> 2, alc = (tid & 3) * 8;    // halves
    const __half* asrc;
    if (MODE == 2) {
        int gr  = min(r0 + alr, nc - 1);
        int tok = g_rows_token[e * CAP_ + gr];
        asrc = A + (size_t)tok * D_ + alc;
    } else if (MODE == 3) {
        asrc = A + ((size_t)e * CAP_ + r0 + alr) * H_ + alc;
    } else {
        asrc = A + (size_t)(r0 + alr) * KLEN + alc;
    }
    const int bkr = tid >> 4, bcf = (tid & 15) * 8;   // halves
    const size_t eb = (MODE == 2) ? (size_t)e * D_ * H_
                    : ((MODE == 3) ? (size_t)e * H_ * D_ : 0);
    const __half* b1src = B1 + eb + (size_t)bkr * NTOT + n0 + bcf;
    const __half* b3src = DUAL ? (B3 + eb + (size_t)bkr * NTOT + n0 + bcf) : A;
    const uint32_t adst = (uint32_t)(alr * ARB + alc * 2);
    const uint32_t bdst = (uint32_t)(bkr * BRB + bcf * 2);

    auto issue = [&](int c, int s) {
        uint32_t base = sb0 + (uint32_t)s * STAGE;
        cp16(base + adst, asrc + c * 32);
        cp16(base + ABYTES + bdst, b1src + (size_t)c * 32 * NTOT);
        if (DUAL)
            cp16(base + ABYTES + BBYTES + bdst, b3src + (size_t)c * 32 * NTOT);
        cp_commit();
    };

    // ---- accumulators ----
    float acc1[2][NT][4];
    float acc3[DUAL ? 2 : 1][DUAL ? NT : 1][4];
    #pragma unroll
    for (int i = 0; i < 2; ++i)
        #pragma unroll
        for (int j = 0; j < NT; ++j)
            #pragma unroll
            for (int k = 0; k < 4; ++k) {
                acc1[i][j][k] = 0.f;
                if (DUAL) acc3[i][j][k] = 0.f;
            }

    const int g = lane >> 2, q = lane & 3;
    const int wr = (wid >> 2) * 32, wc = (wid & 3) * 32;   // 4x4 warp grid

    // ldmatrix lane offsets
    const uint32_t aoffL = (uint32_t)((wr + (lane & 15)) * ARB + ((lane >> 4) & 1) * 16);
    const uint32_t boffL = (uint32_t)(((((lane >> 3) & 1) * 8) + (lane & 7)) * BRB
                                      + (wc + ((lane >> 4) & 1) * 8) * 2);

    // ---- prologue: fill S-1 stages ----
    #pragma unroll
    for (int i = 0; i < S - 1; ++i) issue(i, i);
    cp_wait<S - 2>();
    __syncthreads();

    // ---- mainloop: one barrier per chunk, 2 x k16 slices ----
    for (int c = 0; c < NCH; ++c) {
        const int s = c % S;
        if (c + S - 1 < NCH) issue(c + S - 1, (c + S - 1) % S);

        const uint32_t sBase = sb0 + (uint32_t)s * STAGE;
        #pragma unroll
        for (int ks = 0; ks < 2; ++ks) {
            const int kk = ks * 16;
            uint32_t af[2][4];
            ldsm_x4(af[0], sBase + aoffL + kk * 2);
            ldsm_x4(af[1], sBase + aoffL + 16 * ARB + kk * 2);
            #pragma unroll
            for (int ntp = 0; ntp < 2; ++ntp) {
                uint32_t bb[4];
                ldsm_x4t(bb, sBase + ABYTES + boffL + kk * BRB + ntp * 32);
                mma16(acc1[0][2*ntp],   af[0], bb);
                mma16(acc1[1][2*ntp],   af[1], bb);
                mma16(acc1[0][2*ntp+1], af[0], bb + 2);
                mma16(acc1[1][2*ntp+1], af[1], bb + 2);
                if (DUAL) {
                    uint32_t b3[4];
                    ldsm_x4t(b3, sBase + ABYTES + BBYTES + boffL + kk * BRB + ntp * 32);
                    mma16(acc3[0][2*ntp],   af[0], b3);
                    mma16(acc3[1][2*ntp],   af[1], b3);
                    mma16(acc3[0][2*ntp+1], af[0], b3 + 2);
                    mma16(acc3[1][2*ntp+1], af[1], b3 + 2);
                }
            }
        }
        cp_wait<S - 2>();
        __syncthreads();
    }

    // ---- epilogue ----
    #pragma unroll
    for (int mt = 0; mt < 2; ++mt) {
        #pragma unroll
        for (int h = 0; h < 2; ++h) {
            const int grow = r0 + wr + 16 * mt + 8 * h + g;
            const bool valid = EXPERT ? (grow < nc) : true;
            if (!valid) continue;
            #pragma unroll
            for (int nt = 0; nt < NT; ++nt) {
                const int col = n0 + wc + 8 * nt + 2 * q;
                float v0 = acc1[mt][nt][2 * h];
                float v1 = acc1[mt][nt][2 * h + 1];
                if (DUAL) {
                    v0 = silu_f(v0) * acc3[mt][nt][2 * h];
                    v1 = silu_f(v1) * acc3[mt][nt][2 * h + 1];
                    __half* oh;
                    if (MODE == 0) oh = (__half*)OutV + (size_t)grow * HS_ + col;
                    else           oh = (__half*)OutV + ((size_t)e * CAP_ + grow) * H_ + col;
                    *(uint32_t*)oh = pack_h2(v1, v0);
                } else {
                    float* of;
                    if (MODE == 1) of = (float*)OutV + (size_t)grow * D_ + col;
                    else {
                        int p = g_slot_pair[e * CAP_ + grow];
                        of = (float*)OutV + (size_t)p * D_ + col;
                    }
                    float2 vv; vv.x = v0; vv.y = v1;
                    *(float2*)of = vv;
                }
            }
        }
    }
}

// ---------------- combine: y = z + sum_k w_k * Obuf[pair] -------------------
__global__ __launch_bounds__(256) void combine_kernel(float* __restrict__ y)
{
    int t = blockIdx.x;
    int c4 = threadIdx.x;
    size_t off = (size_t)t * D_ + c4 * 4;
    float4 acc = *(float4*)(y + off);
    #pragma unroll
    for (int k = 0; k < TOPK_; ++k) {
        int p = t * TOPK_ + k;
        float w = g_pair_wc[p];
        float4 o = *(const float4*)(g_Obuf + (size_t)p * D_ + c4 * 4);
        acc.x = fmaf(w, o.x, acc.x);
        acc.y = fmaf(w, o.y, acc.y);
        acc.z = fmaf(w, o.z, acc.z);
        acc.w = fmaf(w, o.w, acc.w);
    }
    *(float4*)(y + off) = acc;
}

// ---------------- launch -----------------------------------------------------
extern "C" void kernel_launch(void* const* d_in, const int* in_sizes, int n_in,
                              void* d_out, int out_size)
{
    const float* x   = (const float*)d_in[0];
    const float* Wg  = (const float*)d_in[1];
    const float* W1  = (const float*)d_in[2];
    const float* W2  = (const float*)d_in[3];
    const float* W3  = (const float*)d_in[4];
    const float* Ws1 = (const float*)d_in[5];
    const float* Ws2 = (const float*)d_in[6];
    const float* Ws3 = (const float*)d_in[7];
    float* y = (float*)d_out;

    const int SMEM_DUAL   = 3 * (128*80 + 2 * 32*272);  // 82944
    const int SMEM_SINGLE = 4 * (128*80 + 1 * 32*272);  // 75776
    cudaFuncSetAttribute(gemm_mma<0>, cudaFuncAttributeMaxDynamicSharedMemorySize, SMEM_DUAL);
    cudaFuncSetAttribute(gemm_mma<1>, cudaFuncAttributeMaxDynamicSharedMemorySize, SMEM_SINGLE);
    cudaFuncSetAttribute(gemm_mma<2>, cudaFuncAttributeMaxDynamicSharedMemorySize, SMEM_DUAL);
    cudaFuncSetAttribute(gemm_mma<3>, cudaFuncAttributeMaxDynamicSharedMemorySize, SMEM_SINGLE);

    void *p_xh, *p_w1h, *p_w3h, *p_w2h, *p_ws1h, *p_ws3h, *p_ws2h;
    void *p_gsh, *p_gbufh, *p_obuf;
    cudaGetSymbolAddress(&p_xh,    g_xh);
    cudaGetSymbolAddress(&p_w1h,   g_W1h);
    cudaGetSymbolAddress(&p_w3h,   g_W3h);
    cudaGetSymbolAddress(&p_w2h,   g_W2h);
    cudaGetSymbolAddress(&p_ws1h,  g_Ws1h);
    cudaGetSymbolAddress(&p_ws3h,  g_Ws3h);
    cudaGetSymbolAddress(&p_ws2h,  g_Ws2h);
    cudaGetSymbolAddress(&p_gsh,   g_Gsh);
    cudaGetSymbolAddress(&p_gbufh, g_Gbufh);
    cudaGetSymbolAddress(&p_obuf,  g_Obuf);

    // gating + dispatch (reads fp32 x)
    gate_kernel<<<T_, 256>>>(x, Wg);
    zero_counts_kernel<<<1, 32>>>();
    dispatch_kernel<<<P_/256, 256>>>();

    // prepass: convert x + all weights to fp16 (~350MB traffic)
    const int n4_x  = T_*D_/4, n4_w = E_*D_*H_/4, n4_ws = D_*HS_/4;
    f32_to_f16<<<(n4_x  + 255)/256, 256>>>((const float4*)x,   (uint2*)p_xh,   n4_x);
    f32_to_f16<<<(n4_w  + 255)/256, 256>>>((const float4*)W1,  (uint2*)p_w1h,  n4_w);
    f32_to_f16<<<(n4_w  + 255)/256, 256>>>((const float4*)W3,  (uint2*)p_w3h,  n4_w);
    f32_to_f16<<<(n4_w  + 255)/256, 256>>>((const float4*)W2,  (uint2*)p_w2h,  n4_w);
    f32_to_f16<<<(n4_ws + 255)/256, 256>>>((const float4*)Ws1, (uint2*)p_ws1h, n4_ws);
    f32_to_f16<<<(n4_ws + 255)/256, 256>>>((const float4*)Ws3, (uint2*)p_ws3h, n4_ws);
    f32_to_f16<<<(n4_ws + 255)/256, 256>>>((const float4*)Ws2, (uint2*)p_ws2h, n4_ws);

    // shared expert (writes all of y via MODE 1)
    gemm_mma<0><<<dim3(HS_/128, T_/128), 512, SMEM_DUAL>>>(
        (const __half*)p_xh, (const __half*)p_ws1h, (const __half*)p_ws3h, p_gsh);
    gemm_mma<1><<<dim3(D_/128, T_/128), 512, SMEM_SINGLE>>>(
        (const __half*)p_gsh, (const __half*)p_ws2h, nullptr, y);

    // routed experts
    gemm_mma<2><<<dim3(H_/128, CAP_/128, E_), 512, SMEM_DUAL>>>(
        (const __half*)p_xh, (const __half*)p_w1h, (const __half*)p_w3h, p_gbufh);
    gemm_mma<3><<<dim3(D_/128, CAP_/128, E_), 512, SMEM_SINGLE>>>(
        (const __half*)p_gbufh, (const __half*)p_w2h, nullptr, p_obuf);

    // deterministic combine
    combine_kernel<<<T_, 256>>>(y);
}

// round 15
// speedup vs baseline: 2.1792x; 1.0122x over previous
#include <cuda_runtime.h>
#include <cuda_fp16.h>
#include <math.h>
#include <stdint.h>

// Problem shapes (fixed by the dataset)
#define T_    4096
#define D_    1024
#define H_    512
#define E_    32
#define TOPK_ 4
#define CAP_  2048
#define HS_   1024
#define P_    (T_*TOPK_)

// ---------------- scratch (device globals) ----------------------------------
__device__ int   g_topk_idx[P_];
__device__ float g_topk_w[P_];
__device__ float g_pair_wc[P_];
__device__ int   g_counts[E_];
__device__ int   g_rows_token[E_*CAP_];
__device__ int   g_slot_pair[E_*CAP_];
// fp16 copies of inputs
__device__ __align__(256) __half g_xh[(size_t)T_*D_];
__device__ __align__(256) __half g_W1h[(size_t)E_*D_*H_];
__device__ __align__(256) __half g_W3h[(size_t)E_*D_*H_];
__device__ __align__(256) __half g_W2h[(size_t)E_*H_*D_];
__device__ __align__(256) __half g_Ws1h[(size_t)D_*HS_];
__device__ __align__(256) __half g_Ws3h[(size_t)D_*HS_];
__device__ __align__(256) __half g_Ws2h[(size_t)HS_*D_];
// intermediates
__device__ __align__(256) __half g_Gsh[(size_t)T_*HS_];      // shared hidden
__device__ __align__(256) __half g_Gbufh[(size_t)E_*CAP_*H_];// expert hidden
__device__ __align__(256) float  g_Obuf[(size_t)P_*D_];      // per-pair outputs

// ---------------- helpers ----------------------------------------------------
__device__ __forceinline__ uint32_t smem_u32(const void* p) {
    uint32_t a;
    asm("{ .reg .u64 t; cvta.to.shared.u64 t, %1; cvt.u32.u64 %0, t; }"
        : "=r"(a) : "l"(p));
    return a;
}
__device__ __forceinline__ uint32_t pack_h2(float hi, float lo) {
    uint32_t d;
    asm("cvt.rn.f16x2.f32 %0, %1, %2;" : "=r"(d) : "f"(hi), "f"(lo));
    return d;
}
__device__ __forceinline__ void cp16(uint32_t saddr, const void* g) {
    asm volatile("cp.async.cg.shared.global [%0], [%1], 16;"
                 :: "r"(saddr), "l"(g) : "memory");
}
__device__ __forceinline__ void cp_commit() {
    asm volatile("cp.async.commit_group;" ::: "memory");
}
template<int N>
__device__ __forceinline__ void cp_wait() {
    asm volatile("cp.async.wait_group %0;" :: "n"(N) : "memory");
}
__device__ __forceinline__ void ldsm_x4(uint32_t* r, uint32_t a) {
    asm volatile("ldmatrix.sync.aligned.m8n8.x4.shared.b16 {%0,%1,%2,%3}, [%4];"
        : "=r"(r[0]), "=r"(r[1]), "=r"(r[2]), "=r"(r[3]) : "r"(a));
}
__device__ __forceinline__ void ldsm_x4t(uint32_t* r, uint32_t a) {
    asm volatile("ldmatrix.sync.aligned.m8n8.x4.trans.shared.b16 {%0,%1,%2,%3}, [%4];"
        : "=r"(r[0]), "=r"(r[1]), "=r"(r[2]), "=r"(r[3]) : "r"(a));
}
__device__ __forceinline__ void mma16(float* c, const uint32_t* a, const uint32_t* b) {
    asm volatile(
        "mma.sync.aligned.m16n8k16.row.col.f32.f16.f16.f32 "
        "{%0,%1,%2,%3}, {%4,%5,%6,%7}, {%8,%9}, {%0,%1,%2,%3};"
        : "+f"(c[0]), "+f"(c[1]), "+f"(c[2]), "+f"(c[3])
        : "r"(a[0]), "r"(a[1]), "r"(a[2]), "r"(a[3]), "r"(b[0]), "r"(b[1]));
}
__device__ __forceinline__ float silu_f(float h) {
    return h / (1.0f + expf(-h));
}

// ---------------- fused prepass: fp32 -> fp16 for x + all weights -----------
// Segment boundaries in float4 units.
#define N_X4   (T_*D_/4)                 // 1048576
#define N_W4   (E_*D_*H_/4)              // 4194304
#define N_WS4  (D_*HS_/4)                // 262144
#define CB0    (N_X4)
#define CB1    (CB0 + N_W4)
#define CB2    (CB1 + N_W4)
#define CB3    (CB2 + N_W4)
#define CB4    (CB3 + N_WS4)
#define CB5    (CB4 + N_WS4)
#define CTOT   (CB5 + N_WS4)             // 14417920 = 3520 * 4096

__global__ __launch_bounds__(1024) void convert_all(
    const float4* __restrict__ x,   const float4* __restrict__ W1,
    const float4* __restrict__ W3,  const float4* __restrict__ W2,
    const float4* __restrict__ Ws1, const float4* __restrict__ Ws3,
    const float4* __restrict__ Ws2)
{
    const size_t base = (size_t)blockIdx.x * 4096 + threadIdx.x;
    #pragma unroll
    for (int j = 0; j < 4; ++j) {
        size_t i = base + (size_t)j * 1024;
        const float4* s; uint2* d; size_t off;
        if (i < CB0)      { s = x;   d = (uint2*)g_xh;   off = i; }
        else if (i < CB1) { s = W1;  d = (uint2*)g_W1h;  off = i - CB0; }
        else if (i < CB2) { s = W3;  d = (uint2*)g_W3h;  off = i - CB1; }
        else if (i < CB3) { s = W2;  d = (uint2*)g_W2h;  off = i - CB2; }
        else if (i < CB4) { s = Ws1; d = (uint2*)g_Ws1h; off = i - CB3; }
        else if (i < CB5) { s = Ws3; d = (uint2*)g_Ws3h; off = i - CB4; }
        else              { s = Ws2; d = (uint2*)g_Ws2h; off = i - CB5; }
        float4 v = s[off];
        uint2 o;
        o.x = pack_h2(v.y, v.x);
        o.y = pack_h2(v.w, v.z);
        d[off] = o;
    }
}

// ---------------- gating -----------------------------------------------------
__global__ __launch_bounds__(256) void gate_kernel(const float* __restrict__ x,
                                                   const float* __restrict__ Wg)
{
    __shared__ float xs[D_];
    __shared__ float red[8][E_];
    __shared__ float probs[E_];
    int t = blockIdx.x, tid = threadIdx.x;
    ((float4*)xs)[tid] = ((const float4*)(x + (size_t)t * D_))[tid];
    __syncthreads();
    int e = tid & 31, seg = tid >> 5, k0 = seg * (D_/8);
    float acc = 0.f;
    #pragma unroll 8
    for (int k = 0; k < D_/8; ++k)
        acc = fmaf(xs[k0 + k], Wg[(size_t)(k0 + k) * E_ + e], acc);
    red[seg][e] = acc;
    __syncthreads();
    if (tid < E_) {
        float s = 0.f;
        #pragma unroll
        for (int i = 0; i < 8; ++i) s += red[i][tid];
        float m = s;
        #pragma unroll
        for (int o = 16; o > 0; o >>= 1) m = fmaxf(m, __shfl_xor_sync(0xffffffffu, m, o));
        float p = expf(s - m);
        float sum = p;
        #pragma unroll
        for (int o = 16; o > 0; o >>= 1) sum += __shfl_xor_sync(0xffffffffu, sum, o);
        probs[tid] = p / sum;
    }
    __syncthreads();
    if (tid == 0) {
        bool used[E_];
        #pragma unroll
        for (int i = 0; i < E_; ++i) used[i] = false;
        for (int k = 0; k < TOPK_; ++k) {
            float best = -1.f; int bi = 0;
            for (int i = 0; i < E_; ++i)
                if (!used[i] && probs[i] > best) { best = probs[i]; bi = i; }
            used[bi] = true;
            g_topk_idx[t * TOPK_ + k] = bi;
            g_topk_w  [t * TOPK_ + k] = best;
        }
    }
}

__global__ void zero_counts_kernel() {
    if (threadIdx.x < E_) g_counts[threadIdx.x] = 0;
}

__global__ void dispatch_kernel() {
    int p = blockIdx.x * blockDim.x + threadIdx.x;
    if (p >= P_) return;
    int e   = g_topk_idx[p];
    int tok = p >> 2;
    int pos = atomicAdd(&g_counts[e], 1);
    if (pos < CAP_) {
        int slot = e * CAP_ + pos;
        g_rows_token[slot] = tok;
        g_slot_pair[slot]  = p;
        g_pair_wc[p]       = g_topk_w[p];
    } else {
        g_pair_wc[p] = 0.0f;
    }
}

// ---------------- unified fp16 ldmatrix GEMM (512 threads, 16 warps) --------
// MODE 0: Gsh   = h(silu(x@Ws1)*(x@Ws3))  dual    MODE 1: y    = Gsh@Ws2
// MODE 2: Gbufh = h(silu(xg@W1)*(xg@W3))  dual    MODE 3: Obuf = Gbufh@W2
// CTA 128x128, warp 32x32 (4x4 grid). fp16 smem; K-chunk 32 (2 x k16 slices);
// 4 stages. A row stride 80B, B row stride 272B (ldmatrix conflict-free).
template<int MODE>
__global__ void __launch_bounds__(512, 1)
gemm_mma(const __half* __restrict__ A,
         const __half* __restrict__ B1,
         const __half* __restrict__ B3,
         void* __restrict__ OutV)
{
    constexpr bool DUAL   = (MODE == 0 || MODE == 2);
    constexpr bool EXPERT = (MODE >= 2);
    constexpr int  KLEN   = (MODE == 3) ? H_ : ((MODE == 1) ? HS_ : D_);
    constexpr int  NTOT   = (MODE == 0) ? HS_ : ((MODE == 2) ? H_ : D_);
    constexpr int  NCH    = KLEN / 32;
    constexpr int  S      = 4;                       // pipeline stages
    constexpr int  NT     = 4;                       // n8 tiles per warp
    constexpr int  ARB    = 80;                      // A smem row bytes
    constexpr int  BRB    = 272;                     // B smem row bytes
    constexpr int  ABYTES = 128 * ARB;               // 10240
    constexpr int  BBYTES = 32 * BRB;                // 8704
    constexpr int  STAGE  = ABYTES + (DUAL ? 2 : 1) * BBYTES;

    extern __shared__ char smem[];
    const uint32_t sb0 = smem_u32(smem);

    const int tid = threadIdx.x;
    const int wid = tid >> 5, lane = tid & 31;
    const int e   = EXPERT ? blockIdx.z : 0;
    const int nc  = EXPERT ? min(g_counts[e], CAP_) : (1 << 30);
    const int r0  = blockIdx.y * 128;
    if (EXPERT && r0 >= nc) return;
    const int n0  = blockIdx.x * 128;

    // ---- cp.async addressing: A 4 thr/row x 1 cp16; B 16 thr/row x 1 cp16 --
    const int alr = tid >> 2, alc = (tid & 3) * 8;    // halves
    const __half* asrc;
    if (MODE == 2) {
        int gr  = min(r0 + alr, nc - 1);
        int tok = g_rows_token[e * CAP_ + gr];
        asrc = A + (size_t)tok * D_ + alc;
    } else if (MODE == 3) {
        asrc = A + ((size_t)e * CAP_ + r0 + alr) * H_ + alc;
    } else {
        asrc = A + (size_t)(r0 + alr) * KLEN + alc;
    }
    const int bkr = tid >> 4, bcf = (tid & 15) * 8;   // halves
    const size_t eb = (MODE == 2) ? (size_t)e * D_ * H_
                    : ((MODE == 3) ? (size_t)e * H_ * D_ : 0);
    const __half* b1src = B1 + eb + (size_t)bkr * NTOT + n0 + bcf;
    const __half* b3src = DUAL ? (B3 + eb + (size_t)bkr * NTOT + n0 + bcf) : A;
    const uint32_t adst = (uint32_t)(alr * ARB + alc * 2);
    const uint32_t bdst = (uint32_t)(bkr * BRB + bcf * 2);

    auto issue = [&](int c, int s) {
        uint32_t base = sb0 + (uint32_t)s * STAGE;
        cp16(base + adst, asrc + c * 32);
        cp16(base + ABYTES + bdst, b1src + (size_t)c * 32 * NTOT);
        if (DUAL)
            cp16(base + ABYTES + BBYTES + bdst, b3src + (size_t)c * 32 * NTOT);
        cp_commit();
    };

    // ---- accumulators ----
    float acc1[2][NT][4];
    float acc3[DUAL ? 2 : 1][DUAL ? NT : 1][4];
    #pragma unroll
    for (int i = 0; i < 2; ++i)
        #pragma unroll
        for (int j = 0; j < NT; ++j)
            #pragma unroll
            for (int k = 0; k < 4; ++k) {
                acc1[i][j][k] = 0.f;
                if (DUAL) acc3[i][j][k] = 0.f;
            }

    const int g = lane >> 2, q = lane & 3;
    const int wr = (wid >> 2) * 32, wc = (wid & 3) * 32;   // 4x4 warp grid

    // ldmatrix lane offsets
    const uint32_t aoffL = (uint32_t)((wr + (lane & 15)) * ARB + ((lane >> 4) & 1) * 16);
    const uint32_t boffL = (uint32_t)(((((lane >> 3) & 1) * 8) + (lane & 7)) * BRB
                                      + (wc + ((lane >> 4) & 1) * 8) * 2);

    // ---- prologue: fill S-1 stages ----
    #pragma unroll
    for (int i = 0; i < S - 1; ++i) issue(i, i);
    cp_wait<S - 2>();
    __syncthreads();

    // ---- mainloop: one barrier per chunk, 2 x k16 slices ----
    for (int c = 0; c < NCH; ++c) {
        const int s = c % S;
        if (c + S - 1 < NCH) issue(c + S - 1, (c + S - 1) % S);

        const uint32_t sBase = sb0 + (uint32_t)s * STAGE;
        #pragma unroll
        for (int ks = 0; ks < 2; ++ks) {
            const int kk = ks * 16;
            uint32_t af[2][4];
            ldsm_x4(af[0], sBase + aoffL + kk * 2);
            ldsm_x4(af[1], sBase + aoffL + 16 * ARB + kk * 2);
            #pragma unroll
            for (int ntp = 0; ntp < 2; ++ntp) {
                uint32_t bb[4];
                ldsm_x4t(bb, sBase + ABYTES + boffL + kk * BRB + ntp * 32);
                mma16(acc1[0][2*ntp],   af[0], bb);
                mma16(acc1[1][2*ntp],   af[1], bb);
                mma16(acc1[0][2*ntp+1], af[0], bb + 2);
                mma16(acc1[1][2*ntp+1], af[1], bb + 2);
                if (DUAL) {
                    uint32_t b3[4];
                    ldsm_x4t(b3, sBase + ABYTES + BBYTES + boffL + kk * BRB + ntp * 32);
                    mma16(acc3[0][2*ntp],   af[0], b3);
                    mma16(acc3[1][2*ntp],   af[1], b3);
                    mma16(acc3[0][2*ntp+1], af[0], b3 + 2);
                    mma16(acc3[1][2*ntp+1], af[1], b3 + 2);
                }
            }
        }
        cp_wait<S - 2>();
        __syncthreads();
    }

    // ---- epilogue ----
    #pragma unroll
    for (int mt = 0; mt < 2; ++mt) {
        #pragma unroll
        for (int h = 0; h < 2; ++h) {
            const int grow = r0 + wr + 16 * mt + 8 * h + g;
            const bool valid = EXPERT ? (grow < nc) : true;
            if (!valid) continue;
            #pragma unroll
            for (int nt = 0; nt < NT; ++nt) {
                const int col = n0 + wc + 8 * nt + 2 * q;
                float v0 = acc1[mt][nt][2 * h];
                float v1 = acc1[mt][nt][2 * h + 1];
                if (DUAL) {
                    v0 = silu_f(v0) * acc3[mt][nt][2 * h];
                    v1 = silu_f(v1) * acc3[mt][nt][2 * h + 1];
                    __half* oh;
                    if (MODE == 0) oh = (__half*)OutV + (size_t)grow * HS_ + col;
                    else           oh = (__half*)OutV + ((size_t)e * CAP_ + grow) * H_ + col;
                    *(uint32_t*)oh = pack_h2(v1, v0);
                } else {
                    float* of;
                    if (MODE == 1) of = (float*)OutV + (size_t)grow * D_ + col;
                    else {
                        int p = g_slot_pair[e * CAP_ + grow];
                        of = (float*)OutV + (size_t)p * D_ + col;
                    }
                    float2 vv; vv.x = v0; vv.y = v1;
                    *(float2*)of = vv;
                }
            }
        }
    }
}

// ---------------- combine: y = z + sum_k w_k * Obuf[pair] -------------------
__global__ __launch_bounds__(256) void combine_kernel(float* __restrict__ y)
{
    int t = blockIdx.x;
    int c4 = threadIdx.x;
    size_t off = (size_t)t * D_ + c4 * 4;
    float4 acc = *(float4*)(y + off);
    #pragma unroll
    for (int k = 0; k < TOPK_; ++k) {
        int p = t * TOPK_ + k;
        float w = g_pair_wc[p];
        float4 o = *(const float4*)(g_Obuf + (size_t)p * D_ + c4 * 4);
        acc.x = fmaf(w, o.x, acc.x);
        acc.y = fmaf(w, o.y, acc.y);
        acc.z = fmaf(w, o.z, acc.z);
        acc.w = fmaf(w, o.w, acc.w);
    }
    *(float4*)(y + off) = acc;
}

// ---------------- launch -----------------------------------------------------
extern "C" void kernel_launch(void* const* d_in, const int* in_sizes, int n_in,
                              void* d_out, int out_size)
{
    const float* x   = (const float*)d_in[0];
    const float* Wg  = (const float*)d_in[1];
    const float* W1  = (const float*)d_in[2];
    const float* W2  = (const float*)d_in[3];
    const float* W3  = (const float*)d_in[4];
    const float* Ws1 = (const float*)d_in[5];
    const float* Ws2 = (const float*)d_in[6];
    const float* Ws3 = (const float*)d_in[7];
    float* y = (float*)d_out;

    const int SMEM_DUAL   = 4 * (128*80 + 2 * 32*272);  // 110592
    const int SMEM_SINGLE = 4 * (128*80 + 1 * 32*272);  // 75776
    cudaFuncSetAttribute(gemm_mma<0>, cudaFuncAttributeMaxDynamicSharedMemorySize, SMEM_DUAL);
    cudaFuncSetAttribute(gemm_mma<1>, cudaFuncAttributeMaxDynamicSharedMemorySize, SMEM_SINGLE);
    cudaFuncSetAttribute(gemm_mma<2>, cudaFuncAttributeMaxDynamicSharedMemorySize, SMEM_DUAL);
    cudaFuncSetAttribute(gemm_mma<3>, cudaFuncAttributeMaxDynamicSharedMemorySize, SMEM_SINGLE);

    void *p_xh, *p_w1h, *p_w3h, *p_w2h, *p_ws1h, *p_ws3h, *p_ws2h;
    void *p_gsh, *p_gbufh, *p_obuf;
    cudaGetSymbolAddress(&p_xh,    g_xh);
    cudaGetSymbolAddress(&p_w1h,   g_W1h);
    cudaGetSymbolAddress(&p_w3h,   g_W3h);
    cudaGetSymbolAddress(&p_w2h,   g_W2h);
    cudaGetSymbolAddress(&p_ws1h,  g_Ws1h);
    cudaGetSymbolAddress(&p_ws3h,  g_Ws3h);
    cudaGetSymbolAddress(&p_ws2h,  g_Ws2h);
    cudaGetSymbolAddress(&p_gsh,   g_Gsh);
    cudaGetSymbolAddress(&p_gbufh, g_Gbufh);
    cudaGetSymbolAddress(&p_obuf,  g_Obuf);

    // fused prepass: convert x + all weights to fp16 in one launch
    convert_all<<<CTOT/4096, 1024>>>(
        (const float4*)x, (const float4*)W1, (const float4*)W3, (const float4*)W2,
        (const float4*)Ws1, (const float4*)Ws3, (const float4*)Ws2);

    // gating + dispatch (reads fp32 x)
    gate_kernel<<<T_, 256>>>(x, Wg);
    zero_counts_kernel<<<1, 32>>>();
    dispatch_kernel<<<P_/256, 256>>>();

    // shared expert (writes all of y via MODE 1)
    gemm_mma<0><<<dim3(HS_/128, T_/128), 512, SMEM_DUAL>>>(
        (const __half*)p_xh, (const __half*)p_ws1h, (const __half*)p_ws3h, p_gsh);
    gemm_mma<1><<<dim3(D_/128, T_/128), 512, SMEM_SINGLE>>>(
        (const __half*)p_gsh, (const __half*)p_ws2h, nullptr, y);

    // routed experts
    gemm_mma<2><<<dim3(H_/128, CAP_/128, E_), 512, SMEM_DUAL>>>(
        (const __half*)p_xh, (const __half*)p_w1h, (const __half*)p_w3h, p_gbufh);
    gemm_mma<3><<<dim3(D_/128, CAP_/128, E_), 512, SMEM_SINGLE>>>(
        (const __half*)p_gbufh, (const __half*)p_w2h, nullptr, p_obuf);

    // deterministic combine
    combine_kernel<<<T_, 256>>>(y);
}